// round 14
// baseline (speedup 1.0000x reference)
#include <cuda_runtime.h>
#include <cuda_fp16.h>
#include <cstdint>

#define NMAX 50000
#define EMAX 800000
#define H 128
#define NBLK 592              // 4 blocks/SM x 148 SMs -> co-resident
#define GSZ (NBLK * 256)
#define MAX_EPT 8             // MAX_EPT*GSZ >= EMAX

// ---------------- scratch (__device__ globals) ------------------------------
__device__ float4 g_aggr[NMAX * (H / 4)];  // segment-sum of nb rows (tf32 bits)
__device__ uint2  g_nbh[NMAX * 32];        // node_embedding as fp16 (256B/row)
__device__ float  g_s[NMAX];               // per-node sum of edge_attr
__device__ float4 g_v3[H / 4];             // relu(W4) @ W3
__device__ int    g_cnt[NMAX + 4];         // degree counts (padded to int4)
__device__ int    g_off[NMAX + 1];         // CSR row offsets
__device__ int    g_cols[EMAX];            // CSR column indices

// grid barrier state (self-resetting across graph replays)
__device__ unsigned g_bar_count = 0;
__device__ unsigned g_bar_sense = 0;

// ---------------------------------------------------------------------------
__device__ __forceinline__ unsigned f2tf32(float f) {
    unsigned u;
    asm("cvt.rna.tf32.f32 %0, %1;" : "=r"(u) : "f"(f));
    return u;
}

__device__ __forceinline__ void mma_tf32(float* c, const unsigned* a,
                                         const unsigned* b) {
    asm volatile(
        "mma.sync.aligned.m16n8k8.row.col.f32.tf32.tf32.f32 "
        "{%0,%1,%2,%3}, {%4,%5,%6,%7}, {%8,%9}, {%0,%1,%2,%3};"
        : "+f"(c[0]), "+f"(c[1]), "+f"(c[2]), "+f"(c[3])
        : "r"(a[0]), "r"(a[1]), "r"(a[2]), "r"(a[3]), "r"(b[0]), "r"(b[1]));
}

__device__ __forceinline__ void grid_bar(unsigned& lsense) {
    __syncthreads();
    if (threadIdx.x == 0) {
        lsense ^= 1u;
        __threadfence();
        unsigned old = atomicAdd(&g_bar_count, 1u);
        if (old == NBLK - 1u) {
            g_bar_count = 0u;
            __threadfence();
            atomicExch(&g_bar_sense, lsense);
        } else {
            while (*(volatile unsigned*)&g_bar_sense != lsense) __nanosleep(32);
        }
        __threadfence();
    }
    __syncthreads();
}

// ---------------------------------------------------------------------------
// Build kernel: P0 zero+convert+v3 | P1 hist (edges->regs) | P2 scan | P3 fill
// ---------------------------------------------------------------------------
__global__ void __launch_bounds__(256, 4)
build_kernel(const void* __restrict__ ei, const float* __restrict__ ea,
             const float* __restrict__ nb, const float* __restrict__ W4,
             const float* __restrict__ W3, int n, int e, int n4, int nbs) {
    __shared__ int s_red[8];
    __shared__ int s_ts[256];
    __shared__ int s_base;

    const int t    = threadIdx.x;
    const int gtid = blockIdx.x * 256 + t;
    unsigned lsense = 0;
    if (t == 0) lsense = *(volatile unsigned*)&g_bar_sense;

    const int* p32 = (const int*)ei;
    const bool is64 = (p32[1] | p32[3] | p32[5] | p32[7]) == 0;
    const long long* p64 = (const long long*)ei;

    // ---- P0: zero cnt/s, fp16 convert, v3 ----------------------------------
    for (int i = gtid; i < n * 32; i += GSZ) {
        float4 v = ((const float4*)nb)[i];
        __half2 h0 = __floats2half2_rn(v.x, v.y);
        __half2 h1 = __floats2half2_rn(v.z, v.w);
        uint2 u;
        u.x = *(unsigned*)&h0;
        u.y = *(unsigned*)&h1;
        g_nbh[i] = u;
    }
    {
        int npad = (n + 3) & ~3;
        for (int i = gtid; i < npad; i += GSZ) g_cnt[i] = 0;
        for (int i = gtid; i < n; i += GSZ) g_s[i] = 0.f;
    }
    if (blockIdx.x == 0 && t < H) {
        float acc = 0.f;
#pragma unroll 8
        for (int c = 0; c < H; ++c) {
            float w = W4[c];
            w = w > 0.f ? w : 0.f;
            acc += w * W3[c * H + t];
        }
        ((float*)g_v3)[t] = acc;
    }
    grid_bar(lsense);

    // ---- P1: histogram; keep (r, c, rank) in registers ---------------------
    int er[MAX_EPT], ec[MAX_EPT], ek[MAX_EPT];
#pragma unroll
    for (int k = 0; k < MAX_EPT; ++k) {
        int idx = gtid + k * GSZ;
        er[k] = -1; ec[k] = 0; ek[k] = 0;
        if (idx < e) {
            int r, c;
            if (is64) { r = (int)p64[idx]; c = (int)p64[e + idx]; }
            else      { r = p32[idx];      c = p32[e + idx]; }
            if ((unsigned)r < (unsigned)n && (unsigned)c < (unsigned)n) {
                er[k] = r; ec[k] = c;
                ek[k] = atomicAdd(&g_cnt[r], 1);
                atomicAdd(&g_s[r], ea[idx]);
            }
        }
    }
    grid_bar(lsense);

    // ---- P2: scan (blocks < nbs) -------------------------------------------
    if ((int)blockIdx.x < nbs) {
        int lane = t & 31, wid = t >> 5;
        int s = 0;
        int lim = blockIdx.x * 256;   // int4 units before this chunk
        for (int i = t; i < lim; i += 256) {
            int4 v = ((const int4*)g_cnt)[i];
            s += v.x + v.y + v.z + v.w;
        }
#pragma unroll
        for (int o = 16; o > 0; o >>= 1) s += __shfl_down_sync(0xffffffffu, s, o);
        if (lane == 0) s_red[wid] = s;
        __syncthreads();
        if (t == 0) {
            int a = 0;
#pragma unroll
            for (int k = 0; k < 8; ++k) a += s_red[k];
            s_base = a;
        }
        __syncthreads();
        int base = s_base;

        int i = blockIdx.x * 256 + t;
        int4 v = (i < n4) ? ((const int4*)g_cnt)[i] : make_int4(0, 0, 0, 0);
        int tot = v.x + v.y + v.z + v.w;
        s_ts[t] = tot;
        __syncthreads();
#pragma unroll
        for (int d = 1; d < 256; d <<= 1) {
            int xv = (t >= d) ? s_ts[t - d] : 0;
            __syncthreads();
            s_ts[t] += xv;
            __syncthreads();
        }
        if (i < n4) {
            int o0 = base + s_ts[t] - tot;
            int o1 = o0 + v.x, o2 = o1 + v.y, o3 = o2 + v.z;
            ((int4*)g_off)[i] = make_int4(o0, o1, o2, o3);
        }
        if ((int)blockIdx.x == nbs - 1 && t == 255) g_off[n] = base + s_ts[255];
    }
    grid_bar(lsense);

    // ---- P3: fill from registers -------------------------------------------
#pragma unroll
    for (int k = 0; k < MAX_EPT; ++k)
        if (er[k] >= 0) g_cols[g_off[er[k]] + ek[k]] = ec[k];
}

// ---------------------------------------------------------------------------
// Aggregate: warp per row, fp16 gathers (8-deep MLP), fp32 acc, tf32 output.
// ---------------------------------------------------------------------------
__global__ void aggr_kernel(int n) {
    int w    = (blockIdx.x * blockDim.x + threadIdx.x) >> 5;
    int lane = threadIdx.x & 31;
    if (w >= n) return;

    int beg = g_off[w], end = g_off[w + 1];
    float4 acc = make_float4(0.f, 0.f, 0.f, 0.f);
    int j = beg;
    for (; j + 8 <= end; j += 8) {
        int cc[8];
#pragma unroll
        for (int q = 0; q < 8; ++q) cc[q] = g_cols[j + q];
        uint2 u[8];
#pragma unroll
        for (int q = 0; q < 8; ++q) u[q] = g_nbh[cc[q] * 32 + lane];
#pragma unroll
        for (int q = 0; q < 8; ++q) {
            float2 a = __half22float2(*(__half2*)&u[q].x);
            float2 b = __half22float2(*(__half2*)&u[q].y);
            acc.x += a.x; acc.y += a.y; acc.z += b.x; acc.w += b.y;
        }
    }
    for (; j < end; ++j) {
        uint2 u = g_nbh[g_cols[j] * 32 + lane];
        float2 a = __half22float2(*(__half2*)&u.x);
        float2 b = __half22float2(*(__half2*)&u.y);
        acc.x += a.x; acc.y += a.y; acc.z += b.x; acc.w += b.y;
    }
    *(uint4*)&g_aggr[w * 32 + lane] =
        make_uint4(f2tf32(acc.x), f2tf32(acc.y), f2tf32(acc.z), f2tf32(acc.w));
}

// ---------------------------------------------------------------------------
// Tensor-core GEMM (tf32 mma.sync), K-extension folding:
//   A' = [aggr(128) | x(8) | s(1) | 0...]  (5 chunks of 32), B' = [W2;W1;v3].
//   out = relu(A' @ B')
// ---------------------------------------------------------------------------
#define AS_STRIDE 36
#define BS_STRIDE 132

__global__ void __launch_bounds__(256, 2)
mma_fused_kernel(const float* __restrict__ x,
                 const float* __restrict__ W1,
                 const float* __restrict__ W2,
                 float* __restrict__ out, int n) {
    __shared__ unsigned As[128 * AS_STRIDE];
    __shared__ unsigned Bs[32 * BS_STRIDE];

    const int t    = threadIdx.x;
    const int lane = t & 31;
    const int w    = t >> 5;
    const int wr0  = (w >> 1) * 32;
    const int wc0  = (w & 1) * 64;
    const int gid  = lane >> 2;
    const int tig  = lane & 3;
    const int rbase = blockIdx.x * 128;

    float acc[2][8][4];
#pragma unroll
    for (int mi = 0; mi < 2; ++mi)
#pragma unroll
        for (int ni = 0; ni < 8; ++ni)
#pragma unroll
            for (int q = 0; q < 4; ++q) acc[mi][ni][q] = 0.f;

    for (int chunk = 0; chunk < 5; ++chunk) {
        __syncthreads();
        if (chunk < 4) {
            for (int i = t; i < 128 * 8; i += 256) {
                int row = i >> 3, q = i & 7;
                int r = rbase + row;
                uint4 v = (r < n) ? *(const uint4*)&g_aggr[r * 32 + chunk * 8 + q]
                                  : make_uint4(0u, 0u, 0u, 0u);
                *(uint4*)&As[row * AS_STRIDE + 4 * q] = v;
            }
            for (int i = t; i < 32 * 32; i += 256) {
                int kk = i >> 5, q = i & 31;
                float4 v = ((const float4*)W2)[(chunk * 32 + kk) * 32 + q];
                *(uint4*)&Bs[kk * BS_STRIDE + 4 * q] =
                    make_uint4(f2tf32(v.x), f2tf32(v.y), f2tf32(v.z), f2tf32(v.w));
            }
        } else {
            for (int i = t; i < 128 * 16; i += 256) {
                int row = i >> 4, kk = i & 15;
                int r = rbase + row;
                float v = 0.f;
                if (r < n) {
                    if (kk < 8)       v = x[r * 8 + kk];
                    else if (kk == 8) v = g_s[r];
                }
                As[row * AS_STRIDE + kk] = f2tf32(v);
            }
            for (int i = t; i < 16 * 128; i += 256) {
                int kk = i >> 7, col = i & 127;
                float v = 0.f;
                if (kk < 8)       v = W1[kk * H + col];
                else if (kk == 8) v = ((const float*)g_v3)[col];
                Bs[kk * BS_STRIDE + col] = f2tf32(v);
            }
        }
        __syncthreads();

        const int ksteps = (chunk < 4) ? 4 : 2;
        for (int ks = 0; ks < ksteps; ++ks) {
            const int k0 = ks * 8;
            unsigned a[2][4], b[8][2];
#pragma unroll
            for (int mi = 0; mi < 2; ++mi) {
                int row = wr0 + mi * 16 + gid;
                a[mi][0] = As[row * AS_STRIDE + k0 + tig];
                a[mi][1] = As[(row + 8) * AS_STRIDE + k0 + tig];
                a[mi][2] = As[row * AS_STRIDE + k0 + tig + 4];
                a[mi][3] = As[(row + 8) * AS_STRIDE + k0 + tig + 4];
            }
#pragma unroll
            for (int ni = 0; ni < 8; ++ni) {
                int col = wc0 + ni * 8 + gid;
                b[ni][0] = Bs[(k0 + tig) * BS_STRIDE + col];
                b[ni][1] = Bs[(k0 + tig + 4) * BS_STRIDE + col];
            }
#pragma unroll
            for (int mi = 0; mi < 2; ++mi)
#pragma unroll
                for (int ni = 0; ni < 8; ++ni)
                    mma_tf32(acc[mi][ni], a[mi], b[ni]);
        }
    }

    // epilogue: relu + store
#pragma unroll
    for (int mi = 0; mi < 2; ++mi) {
#pragma unroll
        for (int half = 0; half < 2; ++half) {
            int r = rbase + wr0 + mi * 16 + gid + half * 8;
            if (r >= n) continue;
#pragma unroll
            for (int ni = 0; ni < 8; ++ni) {
                int col = wc0 + ni * 8 + 2 * tig;
                float v0 = acc[mi][ni][half * 2 + 0];
                float v1 = acc[mi][ni][half * 2 + 1];
                v0 = v0 > 0.f ? v0 : 0.f;
                v1 = v1 > 0.f ? v1 : 0.f;
                ((float2*)out)[r * 64 + (col >> 1)] = make_float2(v0, v1);
            }
        }
    }
}

// ---------------------------------------------------------------------------
extern "C" void kernel_launch(void* const* d_in, const int* in_sizes, int n_in,
                              void* d_out, int out_size) {
    const float* x   = (const float*)d_in[0];
    const void*  ei  = d_in[1];                 // int32 or int64 (device-detected)
    const float* ea  = (const float*)d_in[2];
    const float* nb  = (const float*)d_in[3];
    const float* W1  = (const float*)d_in[4];
    const float* W2  = (const float*)d_in[5];
    const float* W3  = (const float*)d_in[6];
    const float* W4  = (const float*)d_in[7];
    float* out = (float*)d_out;

    const int n   = in_sizes[0] / 8;   // 50000
    const int e   = in_sizes[2];       // 800000
    const int n4  = (n + 3) / 4;       // 12500
    const int nbs = (n4 + 255) / 256;  // 49 scan chunks
    const int ntiles = (n + 127) / 128;

    build_kernel<<<NBLK, 256>>>(ei, ea, nb, W4, W3, n, e, n4, nbs);
    aggr_kernel<<<(n * 32 + 255) / 256, 256>>>(n);
    mma_fused_kernel<<<ntiles, 256>>>(x, W1, W2, out, n);
}

// round 15
// speedup vs baseline: 1.0999x; 1.0999x over previous
#include <cuda_runtime.h>
#include <cuda_fp16.h>
#include <cstdint>

#define NMAX 50000
#define EMAX 800000
#define H 128

// ---------------- scratch (__device__ globals) ------------------------------
__device__ uint2  g_aggrh[NMAX * 32];      // aggr as fp16x4 per lane (8B)
__device__ uint2  g_nbh[NMAX * 32];        // node_embedding as fp16 (256B/row)
__device__ float  g_s[NMAX];               // per-node sum of edge_attr
__device__ float4 g_v3[H / 4];             // relu(W4) @ W3
__device__ int    g_cnt[NMAX + 4];         // degree counts (padded to int4)
__device__ int    g_off[NMAX + 1];         // CSR row offsets
__device__ int    g_rank[EMAX];            // per-edge rank within its row
__device__ int    g_cols[EMAX];            // CSR column indices

// ---------------------------------------------------------------------------
__device__ __forceinline__ unsigned f2tf32(float f) {
    unsigned u;
    asm("cvt.rna.tf32.f32 %0, %1;" : "=r"(u) : "f"(f));
    return u;
}

__device__ __forceinline__ void mma_tf32(float* c, const unsigned* a,
                                         const unsigned* b) {
    asm volatile(
        "mma.sync.aligned.m16n8k8.row.col.f32.tf32.tf32.f32 "
        "{%0,%1,%2,%3}, {%4,%5,%6,%7}, {%8,%9}, {%0,%1,%2,%3};"
        : "+f"(c[0]), "+f"(c[1]), "+f"(c[2]), "+f"(c[3])
        : "r"(a[0]), "r"(a[1]), "r"(a[2]), "r"(a[3]), "r"(b[0]), "r"(b[1]));
}

__device__ __forceinline__ bool ei_is64(const void* ei) {
    const int* p32 = (const int*)ei;
    return (p32[1] | p32[3] | p32[5] | p32[7]) == 0;  // int64 => odd words 0
}

// ---------------------------------------------------------------------------
// Zero cnt/s + v3 = relu(W4)@W3 (block 0).
// ---------------------------------------------------------------------------
__global__ void zero_kernel(const float* __restrict__ W4,
                            const float* __restrict__ W3, int n) {
    int i = blockIdx.x * blockDim.x + threadIdx.x;
    int npad = (n + 3) & ~3;
    if (i < npad) g_cnt[i] = 0;
    if (i < n) g_s[i] = 0.f;
    if (blockIdx.x == 0 && threadIdx.x < H) {
        int j = threadIdx.x;
        float acc = 0.f;
#pragma unroll 8
        for (int c = 0; c < H; ++c) {
            float w = W4[c];
            w = w > 0.f ? w : 0.f;
            acc += w * W3[c * H + j];
        }
        ((float*)g_v3)[j] = acc;
    }
}

// ---------------------------------------------------------------------------
// Fused conv + hist (independent work, disjoint block ranges, no barrier):
//   blocks [0, nconv):      fp32 -> fp16 conversion of node_embedding
//   blocks [nconv, ...):    histogram (2 edges/thread, rank = atomic return)
// conv is bandwidth-bound, hist is latency-bound -> they interleave well.
// ---------------------------------------------------------------------------
__global__ void convhist_kernel(const void* __restrict__ ei,
                                const float* __restrict__ ea,
                                const float* __restrict__ nb,
                                int n, int e, int nconv) {
    int t = threadIdx.x;
    int b = blockIdx.x;

    if (b < nconv) {
        int i = b * 256 + t;
        if (i < n * 32) {
            float4 v = ((const float4*)nb)[i];
            __half2 h0 = __floats2half2_rn(v.x, v.y);
            __half2 h1 = __floats2half2_rn(v.z, v.w);
            uint2 u;
            u.x = *(unsigned*)&h0;
            u.y = *(unsigned*)&h1;
            g_nbh[i] = u;
        }
        return;
    }

    int i2 = (b - nconv) * 256 + t;
    int i  = i2 * 2;
    if (i >= e) return;
    bool is64 = ei_is64(ei);
    bool has1 = (i + 1 < e);

    int r0, r1 = 0;
    if (is64) {
        if (has1) {
            longlong2 v = ((const longlong2*)ei)[i2];
            r0 = (int)v.x; r1 = (int)v.y;
        } else r0 = (int)((const long long*)ei)[i];
    } else {
        if (has1) {
            int2 v = ((const int2*)ei)[i2];
            r0 = v.x; r1 = v.y;
        } else r0 = ((const int*)ei)[i];
    }
    float e0, e1 = 0.f;
    if (has1) { float2 ev = ((const float2*)ea)[i2]; e0 = ev.x; e1 = ev.y; }
    else e0 = ea[i];

    int k0 = 0, k1 = 0;
    if ((unsigned)r0 < (unsigned)n) {
        k0 = atomicAdd(&g_cnt[r0], 1);
        atomicAdd(&g_s[r0], e0);
    }
    if (has1 && (unsigned)r1 < (unsigned)n) {
        k1 = atomicAdd(&g_cnt[r1], 1);
        atomicAdd(&g_s[r1], e1);
    }
    if (has1) ((int2*)g_rank)[i2] = make_int2(k0, k1);
    else g_rank[i] = k0;
}

// ---------------------------------------------------------------------------
// Single-pass scan: block b sums g_cnt[0 .. 1024b) for its base (redundant,
// L2-cached), then locally scans its 1024-count chunk.
// ---------------------------------------------------------------------------
__global__ void scan_kernel(int n, int n4, int nbs) {
    __shared__ int red[8];
    __shared__ int ts[256];
    __shared__ int sbase;
    int t = threadIdx.x;
    int b = blockIdx.x;
    int lane = t & 31, wid = t >> 5;

    int s = 0;
    int lim = b * 256;   // int4 units
    for (int i = t; i < lim; i += 256) {
        int4 v = ((const int4*)g_cnt)[i];
        s += v.x + v.y + v.z + v.w;
    }
#pragma unroll
    for (int o = 16; o > 0; o >>= 1) s += __shfl_down_sync(0xffffffffu, s, o);
    if (lane == 0) red[wid] = s;
    __syncthreads();
    if (t == 0) {
        int a = 0;
#pragma unroll
        for (int k = 0; k < 8; ++k) a += red[k];
        sbase = a;
    }
    __syncthreads();
    int base = sbase;

    int i = b * 256 + t;
    int4 v = (i < n4) ? ((const int4*)g_cnt)[i] : make_int4(0, 0, 0, 0);
    int tot = v.x + v.y + v.z + v.w;
    ts[t] = tot;
    __syncthreads();
#pragma unroll
    for (int d = 1; d < 256; d <<= 1) {
        int xv = (t >= d) ? ts[t - d] : 0;
        __syncthreads();
        ts[t] += xv;
        __syncthreads();
    }
    if (i < n4) {
        int o0 = base + ts[t] - tot;
        int o1 = o0 + v.x, o2 = o1 + v.y, o3 = o2 + v.z;
        ((int4*)g_off)[i] = make_int4(o0, o1, o2, o3);
    }
    if (b == nbs - 1 && t == 255) g_off[n] = base + ts[255];
}

// ---------------------------------------------------------------------------
// Fill: 2 edges/thread, atomic-free — position = off[r] + rank[i].
// ---------------------------------------------------------------------------
__global__ void fill_kernel(const void* __restrict__ ei, int e, int n) {
    int i2 = blockIdx.x * blockDim.x + threadIdx.x;
    int i  = i2 * 2;
    if (i >= e) return;
    bool is64 = ei_is64(ei);
    bool has1 = (i + 1 < e);

    int r0, r1 = 0, c0, c1 = 0;
    if (is64) {
        const long long* p64 = (const long long*)ei;
        if (has1) {
            longlong2 rv = ((const longlong2*)ei)[i2];
            longlong2 cv = ((const longlong2*)(p64 + e))[i2];
            r0 = (int)rv.x; r1 = (int)rv.y;
            c0 = (int)cv.x; c1 = (int)cv.y;
        } else { r0 = (int)p64[i]; c0 = (int)p64[e + i]; }
    } else {
        const int* p32 = (const int*)ei;
        if (has1) {
            int2 rv = ((const int2*)ei)[i2];
            int2 cv = ((const int2*)(p32 + e))[i2];
            r0 = rv.x; r1 = rv.y; c0 = cv.x; c1 = cv.y;
        } else { r0 = p32[i]; c0 = p32[e + i]; }
    }
    int2 rk = has1 ? ((const int2*)g_rank)[i2] : make_int2(g_rank[i], 0);

    if ((unsigned)r0 < (unsigned)n && (unsigned)c0 < (unsigned)n)
        g_cols[g_off[r0] + rk.x] = c0;
    if (has1 && (unsigned)r1 < (unsigned)n && (unsigned)c1 < (unsigned)n)
        g_cols[g_off[r1] + rk.y] = c1;
}

// ---------------------------------------------------------------------------
// Aggregate: warp per row, fp16 gathers (8-deep MLP), fp32 acc, fp16 output.
// (fp16 mantissa == tf32 mantissa -> no extra precision loss vs tf32 bits.)
// ---------------------------------------------------------------------------
__global__ void aggr_kernel(int n) {
    int w    = (blockIdx.x * blockDim.x + threadIdx.x) >> 5;
    int lane = threadIdx.x & 31;
    if (w >= n) return;

    int beg = g_off[w], end = g_off[w + 1];
    float4 acc = make_float4(0.f, 0.f, 0.f, 0.f);
    int j = beg;
    for (; j + 8 <= end; j += 8) {
        int cc[8];
#pragma unroll
        for (int q = 0; q < 8; ++q) cc[q] = g_cols[j + q];
        uint2 u[8];
#pragma unroll
        for (int q = 0; q < 8; ++q) u[q] = g_nbh[cc[q] * 32 + lane];
#pragma unroll
        for (int q = 0; q < 8; ++q) {
            float2 a = __half22float2(*(__half2*)&u[q].x);
            float2 b = __half22float2(*(__half2*)&u[q].y);
            acc.x += a.x; acc.y += a.y; acc.z += b.x; acc.w += b.y;
        }
    }
    for (; j < end; ++j) {
        uint2 u = g_nbh[g_cols[j] * 32 + lane];
        float2 a = __half22float2(*(__half2*)&u.x);
        float2 b = __half22float2(*(__half2*)&u.y);
        acc.x += a.x; acc.y += a.y; acc.z += b.x; acc.w += b.y;
    }
    __half2 h0 = __floats2half2_rn(acc.x, acc.y);
    __half2 h1 = __floats2half2_rn(acc.z, acc.w);
    uint2 o;
    o.x = *(unsigned*)&h0;
    o.y = *(unsigned*)&h1;
    g_aggrh[w * 32 + lane] = o;
}

// ---------------------------------------------------------------------------
// Tensor-core GEMM (tf32 mma.sync), K-extension folding:
//   A' = [aggr(128) | x(8) | s(1) | 0...]  (5 chunks of 32), B' = [W2;W1;v3].
//   out = relu(A' @ B')
// ---------------------------------------------------------------------------
#define AS_STRIDE 36
#define BS_STRIDE 132

__global__ void __launch_bounds__(256, 2)
mma_fused_kernel(const float* __restrict__ x,
                 const float* __restrict__ W1,
                 const float* __restrict__ W2,
                 float* __restrict__ out, int n) {
    __shared__ unsigned As[128 * AS_STRIDE];
    __shared__ unsigned Bs[32 * BS_STRIDE];

    const int t    = threadIdx.x;
    const int lane = t & 31;
    const int w    = t >> 5;
    const int wr0  = (w >> 1) * 32;
    const int wc0  = (w & 1) * 64;
    const int gid  = lane >> 2;
    const int tig  = lane & 3;
    const int rbase = blockIdx.x * 128;

    float acc[2][8][4];
#pragma unroll
    for (int mi = 0; mi < 2; ++mi)
#pragma unroll
        for (int ni = 0; ni < 8; ++ni)
#pragma unroll
            for (int q = 0; q < 4; ++q) acc[mi][ni][q] = 0.f;

    for (int chunk = 0; chunk < 5; ++chunk) {
        __syncthreads();
        if (chunk < 4) {
            // As: aggr rows from fp16 (exact h2->tf32)
            for (int i = t; i < 128 * 8; i += 256) {
                int row = i >> 3, q = i & 7;
                int r = rbase + row;
                uint4 o = make_uint4(0u, 0u, 0u, 0u);
                if (r < n) {
                    uint2 u = g_aggrh[r * 32 + chunk * 8 + q];
                    float2 a = __half22float2(*(__half2*)&u.x);
                    float2 b = __half22float2(*(__half2*)&u.y);
                    o = make_uint4(f2tf32(a.x), f2tf32(a.y),
                                   f2tf32(b.x), f2tf32(b.y));
                }
                *(uint4*)&As[row * AS_STRIDE + 4 * q] = o;
            }
            // Bs: W2 rows [32*chunk, +32)
            for (int i = t; i < 32 * 32; i += 256) {
                int kk = i >> 5, q = i & 31;
                float4 v = ((const float4*)W2)[(chunk * 32 + kk) * 32 + q];
                *(uint4*)&Bs[kk * BS_STRIDE + 4 * q] =
                    make_uint4(f2tf32(v.x), f2tf32(v.y), f2tf32(v.z), f2tf32(v.w));
            }
        } else {
            // As: [x(8) | s(1) | zeros]
            for (int i = t; i < 128 * 16; i += 256) {
                int row = i >> 4, kk = i & 15;
                int r = rbase + row;
                float v = 0.f;
                if (r < n) {
                    if (kk < 8)       v = x[r * 8 + kk];
                    else if (kk == 8) v = g_s[r];
                }
                As[row * AS_STRIDE + kk] = f2tf32(v);
            }
            // Bs: [W1(8) ; v3(1) ; zeros]
            for (int i = t; i < 16 * 128; i += 256) {
                int kk = i >> 7, col = i & 127;
                float v = 0.f;
                if (kk < 8)       v = W1[kk * H + col];
                else if (kk == 8) v = ((const float*)g_v3)[col];
                Bs[kk * BS_STRIDE + col] = f2tf32(v);
            }
        }
        __syncthreads();

        const int ksteps = (chunk < 4) ? 4 : 2;
        for (int ks = 0; ks < ksteps; ++ks) {
            const int k0 = ks * 8;
            unsigned a[2][4], b[8][2];
#pragma unroll
            for (int mi = 0; mi < 2; ++mi) {
                int row = wr0 + mi * 16 + gid;
                a[mi][0] = As[row * AS_STRIDE + k0 + tig];
                a[mi][1] = As[(row + 8) * AS_STRIDE + k0 + tig];
                a[mi][2] = As[row * AS_STRIDE + k0 + tig + 4];
                a[mi][3] = As[(row + 8) * AS_STRIDE + k0 + tig + 4];
            }
#pragma unroll
            for (int ni = 0; ni < 8; ++ni) {
                int col = wc0 + ni * 8 + gid;
                b[ni][0] = Bs[(k0 + tig) * BS_STRIDE + col];
                b[ni][1] = Bs[(k0 + tig + 4) * BS_STRIDE + col];
            }
#pragma unroll
            for (int mi = 0; mi < 2; ++mi)
#pragma unroll
                for (int ni = 0; ni < 8; ++ni)
                    mma_tf32(acc[mi][ni], a[mi], b[ni]);
        }
    }

    // epilogue: relu + store
#pragma unroll
    for (int mi = 0; mi < 2; ++mi) {
#pragma unroll
        for (int half = 0; half < 2; ++half) {
            int r = rbase + wr0 + mi * 16 + gid + half * 8;
            if (r >= n) continue;
#pragma unroll
            for (int ni = 0; ni < 8; ++ni) {
                int col = wc0 + ni * 8 + 2 * tig;
                float v0 = acc[mi][ni][half * 2 + 0];
                float v1 = acc[mi][ni][half * 2 + 1];
                v0 = v0 > 0.f ? v0 : 0.f;
                v1 = v1 > 0.f ? v1 : 0.f;
                ((float2*)out)[r * 64 + (col >> 1)] = make_float2(v0, v1);
            }
        }
    }
}

// ---------------------------------------------------------------------------
extern "C" void kernel_launch(void* const* d_in, const int* in_sizes, int n_in,
                              void* d_out, int out_size) {
    const float* x   = (const float*)d_in[0];
    const void*  ei  = d_in[1];                 // int32 or int64 (device-detected)
    const float* ea  = (const float*)d_in[2];
    const float* nb  = (const float*)d_in[3];
    const float* W1  = (const float*)d_in[4];
    const float* W2  = (const float*)d_in[5];
    const float* W3  = (const float*)d_in[6];
    const float* W4  = (const float*)d_in[7];
    float* out = (float*)d_out;

    const int n   = in_sizes[0] / 8;   // 50000
    const int e   = in_sizes[2];       // 800000
    const int n4  = (n + 3) / 4;       // 12500
    const int nbs = (n4 + 255) / 256;  // 49 scan chunks
    const int ntiles = (n + 127) / 128;
    const int e2  = (e + 1) / 2;       // edge pairs
    const int nconv = (n * 32 + 255) / 256;       // 6250 conv blocks
    const int nhist = (e2 + 255) / 256;           // 1563 hist blocks

    zero_kernel<<<(n + 255) / 256, 256>>>(W4, W3, n);
    convhist_kernel<<<nconv + nhist, 256>>>(ei, ea, nb, n, e, nconv);
    scan_kernel<<<nbs, 256>>>(n, n4, nbs);
    fill_kernel<<<(e2 + 255) / 256, 256>>>(ei, e, n);
    aggr_kernel<<<(n * 32 + 255) / 256, 256>>>(n);
    mma_fused_kernel<<<ntiles, 256>>>(x, W1, W2, out, n);
}